// round 5
// baseline (speedup 1.0000x reference)
#include <cuda_runtime.h>
#include <cuda_bf16.h>
#include <stdint.h>

// Plain-sm_103-legal implementation: HMMA via mma.sync (sm_80 PTX), ldmatrix,
// no tcgen05/TMEM/mbarrier. Single kernel, single launch.

static constexpr int BATCH = 16;
static constexpr int LSEQ  = 2048;
static constexpr int DHEAD = 128;
static constexpr int TQ    = 128;   // q rows per CTA
static constexpr int TKN   = 128;   // keys per tile
static constexpr int NKT   = LSEQ / TKN;

static constexpr int PAD    = 136;            // bf16 row stride (16B pad: conflict-free ldmatrix)
static constexpr int TILE_E = TQ * PAD;       // bf16 elems per tile buffer
// smem layout (bf16 units)
static constexpr int SQH = 0;
static constexpr int SQL = 1 * TILE_E;
static constexpr int SKH = 2 * TILE_E;
static constexpr int SKL = 3 * TILE_E;
static constexpr int SVH = 4 * TILE_E;
static constexpr int SVL = 5 * TILE_E;
static constexpr int SMEM_BYTES = 6 * TILE_E * 2;   // 208896 B

// ---------------- small helpers ----------------
__device__ __forceinline__ uint32_t smem_u32(const void* p) {
    uint32_t a;
    asm("{ .reg .u64 t; cvta.to.shared.u64 t, %1; cvt.u32.u64 %0, t; }" : "=r"(a) : "l"(p));
    return a;
}
__device__ __forceinline__ uint32_t pack2(__nv_bfloat16 a, __nv_bfloat16 b) {
    return (uint32_t)__bfloat16_as_ushort(a) | ((uint32_t)__bfloat16_as_ushort(b) << 16);
}
__device__ __forceinline__ void ldsm_x4(uint32_t& r0, uint32_t& r1, uint32_t& r2, uint32_t& r3, uint32_t addr) {
    asm volatile("ldmatrix.sync.aligned.m8n8.x4.shared.b16 {%0,%1,%2,%3}, [%4];"
                 : "=r"(r0), "=r"(r1), "=r"(r2), "=r"(r3) : "r"(addr));
}
__device__ __forceinline__ void ldsm_x2(uint32_t& r0, uint32_t& r1, uint32_t addr) {
    asm volatile("ldmatrix.sync.aligned.m8n8.x2.shared.b16 {%0,%1}, [%2];"
                 : "=r"(r0), "=r"(r1) : "r"(addr));
}
__device__ __forceinline__ void ldsm_x2_t(uint32_t& r0, uint32_t& r1, uint32_t addr) {
    asm volatile("ldmatrix.sync.aligned.m8n8.x2.trans.shared.b16 {%0,%1}, [%2];"
                 : "=r"(r0), "=r"(r1) : "r"(addr));
}
// D += A * B  (m16n8k16, row.col, bf16 in, f32 accum)
__device__ __forceinline__ void mma16816(float* d, const uint32_t* a, const uint32_t* b) {
    asm volatile("mma.sync.aligned.m16n8k16.row.col.f32.bf16.bf16.f32 "
                 "{%0,%1,%2,%3}, {%4,%5,%6,%7}, {%8,%9}, {%0,%1,%2,%3};"
                 : "+f"(d[0]), "+f"(d[1]), "+f"(d[2]), "+f"(d[3])
                 : "r"(a[0]), "r"(a[1]), "r"(a[2]), "r"(a[3]), "r"(b[0]), "r"(b[1]));
}

// fp32 tile [128 x 128] -> bf16 hi/lo into padded row-major smem
__device__ __forceinline__ void stage_split(const float* __restrict__ g,
                                            __nv_bfloat16* hi, __nv_bfloat16* lo, int tid) {
    #pragma unroll 4
    for (int i = tid * 4; i < TQ * DHEAD; i += 256 * 4) {
        int row = i >> 7, col = i & 127;
        float4 f = *reinterpret_cast<const float4*>(g + (size_t)row * DHEAD + col);
        __nv_bfloat16 h0 = __float2bfloat16_rn(f.x), h1 = __float2bfloat16_rn(f.y);
        __nv_bfloat16 h2 = __float2bfloat16_rn(f.z), h3 = __float2bfloat16_rn(f.w);
        __nv_bfloat16 l0 = __float2bfloat16_rn(f.x - __bfloat162float(h0));
        __nv_bfloat16 l1 = __float2bfloat16_rn(f.y - __bfloat162float(h1));
        __nv_bfloat16 l2 = __float2bfloat16_rn(f.z - __bfloat162float(h2));
        __nv_bfloat16 l3 = __float2bfloat16_rn(f.w - __bfloat162float(h3));
        int o = row * PAD + col;
        *reinterpret_cast<uint2*>(hi + o) = make_uint2(pack2(h0, h1), pack2(h2, h3));
        *reinterpret_cast<uint2*>(lo + o) = make_uint2(pack2(l0, l1), pack2(l2, l3));
    }
}

__global__ void __launch_bounds__(256, 1)
fmha_ln_hmma(const float* __restrict__ Q, const float* __restrict__ K,
             const float* __restrict__ V, const float* __restrict__ MASK,
             const float* __restrict__ GAMMA, const float* __restrict__ BETA,
             float* __restrict__ OUT) {
    extern __shared__ __nv_bfloat16 sm[];
    const int tid = threadIdx.x;
    const int w   = tid >> 5;          // 8 warps
    const int l   = tid & 31;
    const int b   = blockIdx.y;
    const int q0  = blockIdx.x * TQ;

    const int qr  = (l >> 2);          // quad row 0..7
    const int qc2 = (l & 3) * 2;       // col pair base 0,2,4,6
    const int r1  = 16 * w + qr;       // warp-local row (second row = r1+8)

    // stage Q hi/lo once
    stage_split(Q + ((size_t)(b * LSEQ + q0)) * DHEAD, sm + SQH, sm + SQL, tid);

    const uint32_t smb = smem_u32(sm);
    // ldmatrix address lane-offsets (bytes), precomputed per thread
    // A-frags (x4, non-trans): lanes 0-7 rows+0 k+0 | 8-15 rows+8 k+0 | 16-23 rows+0 k+8 | 24-31 rows+8 k+8
    const int a_row = 16 * w + (l & 7) + ((l >> 3) & 1) * 8;
    const int a_col = ((l >> 4) << 3);
    const uint32_t a_off = (uint32_t)(a_row * PAD + a_col) * 2;
    // K b-frags (x2, non-trans): lanes 0-7 rows n8+l k+0 | 8-15 rows n8+(l-8) k+8
    const int lk = l & 15;
    const uint32_t kb_off = (uint32_t)((lk & 7) * PAD + (lk >> 3) * 8) * 2;
    // V b-frags (x2, trans): lanes 0-15 rows 16s+lk, col d8
    const uint32_t vb_off = (uint32_t)(lk * PAD) * 2;

    float o[16][4];
    #pragma unroll
    for (int n = 0; n < 16; ++n)
        { o[n][0] = 0.f; o[n][1] = 0.f; o[n][2] = 0.f; o[n][3] = 0.f; }
    float Z1 = 0.f, Z2 = 0.f;

    const float* mrow1 = MASK + (size_t)(q0 + r1) * LSEQ;
    const float* mrow2 = mrow1 + 8 * LSEQ;

    for (int kt = 0; kt < NKT; ++kt) {
        __syncthreads();   // prior-iteration readers done before restaging K/V
        stage_split(K + ((size_t)(b * LSEQ + kt * TKN)) * DHEAD, sm + SKH, sm + SKL, tid);
        stage_split(V + ((size_t)(b * LSEQ + kt * TKN)) * DHEAD, sm + SVH, sm + SVL, tid);
        __syncthreads();

        // ---- S = Qhi*Khi + Qhi*Klo + Qlo*Khi ----
        float c[16][4];
        #pragma unroll
        for (int n = 0; n < 16; ++n)
            { c[n][0] = 0.f; c[n][1] = 0.f; c[n][2] = 0.f; c[n][3] = 0.f; }

        #pragma unroll 1
        for (int pass = 0; pass < 3; ++pass) {
            const uint32_t qbase = smb + ((pass == 2) ? SQL : SQH) * 2 + a_off;
            const uint32_t kbase = smb + ((pass == 1) ? SKL : SKH) * 2 + kb_off;
            #pragma unroll
            for (int kk = 0; kk < 8; ++kk) {
                uint32_t a[4];
                ldsm_x4(a[0], a[1], a[2], a[3], qbase + kk * 32);
                #pragma unroll
                for (int n = 0; n < 16; ++n) {
                    uint32_t bf[2];
                    ldsm_x2(bf[0], bf[1], kbase + (uint32_t)(n * 8 * PAD * 2 + kk * 32));
                    mma16816(c[n], a, bf);
                }
            }
        }

        // ---- P = exp(S + mask); pack into A-frags; Z += row sums ----
        uint32_t phi[8][4], plo[8][4];
        #pragma unroll
        for (int n = 0; n < 16; ++n) {
            const int cb = kt * TKN + 8 * n + qc2;
            const float2 m1 = *reinterpret_cast<const float2*>(mrow1 + cb);
            const float2 m2 = *reinterpret_cast<const float2*>(mrow2 + cb);
            float e0 = __expf(c[n][0] + m1.x);
            float e1 = __expf(c[n][1] + m1.y);
            float e2 = __expf(c[n][2] + m2.x);
            float e3 = __expf(c[n][3] + m2.y);
            Z1 += e0 + e1;
            Z2 += e2 + e3;
            __nv_bfloat16 h0 = __float2bfloat16_rn(e0), h1 = __float2bfloat16_rn(e1);
            __nv_bfloat16 h2 = __float2bfloat16_rn(e2), h3 = __float2bfloat16_rn(e3);
            const int s = n >> 1, hiHalf = n & 1;   // a-regs: +2 for k-high half
            phi[s][hiHalf * 2 + 0] = pack2(h0, h1);
            phi[s][hiHalf * 2 + 1] = pack2(h2, h3);
            plo[s][hiHalf * 2 + 0] = pack2(__float2bfloat16_rn(e0 - __bfloat162float(h0)),
                                           __float2bfloat16_rn(e1 - __bfloat162float(h1)));
            plo[s][hiHalf * 2 + 1] = pack2(__float2bfloat16_rn(e2 - __bfloat162float(h2)),
                                           __float2bfloat16_rn(e3 - __bfloat162float(h3)));
        }
        // NOTE: a-frag order is {rowL,kL},{rowH,kL},{rowL,kH},{rowH,kH} = [0],[1],[2],[3]
        // mapping above placed: tile 2s -> [0],[1]; tile 2s+1 -> [2],[3]  (correct)

        // ---- O += Phi*Vhi + Plo*Vhi + Phi*Vlo ----
        const uint32_t vhb = smb + SVH * 2 + vb_off;
        const uint32_t vlb = smb + SVL * 2 + vb_off;
        #pragma unroll 2
        for (int n = 0; n < 16; ++n) {          // d-tile
            #pragma unroll
            for (int s = 0; s < 8; ++s) {       // k-step (j)
                const uint32_t off = (uint32_t)(s * 16 * PAD * 2 + n * 16);
                uint32_t bh[2], bl[2];
                ldsm_x2_t(bh[0], bh[1], vhb + off);
                mma16816(o[n], phi[s], bh);
                mma16816(o[n], plo[s], bh);
                ldsm_x2_t(bl[0], bl[1], vlb + off);
                mma16816(o[n], phi[s], bl);
            }
        }
    }

    // ---- reduce Z across the quad (lanes sharing the same rows) ----
    Z1 += __shfl_xor_sync(0xffffffffu, Z1, 1);
    Z1 += __shfl_xor_sync(0xffffffffu, Z1, 2);
    Z2 += __shfl_xor_sync(0xffffffffu, Z2, 1);
    Z2 += __shfl_xor_sync(0xffffffffu, Z2, 2);
    const float zi1 = 1.0f / Z1, zi2 = 1.0f / Z2;

    // ---- LayerNorm stats per row (128 cols; 32 per lane, quad-reduced) ----
    float s1a = 0.f, s1b = 0.f, s2a = 0.f, s2b = 0.f;
    #pragma unroll
    for (int n = 0; n < 16; ++n) {
        float x0 = o[n][0] * zi1, x1 = o[n][1] * zi1;
        float x2 = o[n][2] * zi2, x3 = o[n][3] * zi2;
        s1a += x0 + x1;  s1b += x0 * x0 + x1 * x1;
        s2a += x2 + x3;  s2b += x2 * x2 + x3 * x3;
    }
    s1a += __shfl_xor_sync(0xffffffffu, s1a, 1); s1a += __shfl_xor_sync(0xffffffffu, s1a, 2);
    s1b += __shfl_xor_sync(0xffffffffu, s1b, 1); s1b += __shfl_xor_sync(0xffffffffu, s1b, 2);
    s2a += __shfl_xor_sync(0xffffffffu, s2a, 1); s2a += __shfl_xor_sync(0xffffffffu, s2a, 2);
    s2b += __shfl_xor_sync(0xffffffffu, s2b, 1); s2b += __shfl_xor_sync(0xffffffffu, s2b, 2);

    const float mu1 = s1a * (1.0f / 128.0f);
    const float v1  = fmaxf(s1b * (1.0f / 128.0f) - mu1 * mu1, 0.0f);
    const float rs1 = rsqrtf(v1 + 1e-5f);
    const float mu2 = s2a * (1.0f / 128.0f);
    const float v2  = fmaxf(s2b * (1.0f / 128.0f) - mu2 * mu2, 0.0f);
    const float rs2 = rsqrtf(v2 + 1e-5f);

    float* orow1 = OUT + ((size_t)(b * LSEQ + q0 + r1)) * DHEAD;
    float* orow2 = orow1 + 8 * DHEAD;
    #pragma unroll
    for (int n = 0; n < 16; ++n) {
        const int cb = 8 * n + qc2;
        const float2 g2 = *reinterpret_cast<const float2*>(GAMMA + cb);
        const float2 b2 = *reinterpret_cast<const float2*>(BETA + cb);
        float2 y1, y2;
        y1.x = (o[n][0] * zi1 - mu1) * rs1 * g2.x + b2.x;
        y1.y = (o[n][1] * zi1 - mu1) * rs1 * g2.y + b2.y;
        y2.x = (o[n][2] * zi2 - mu2) * rs2 * g2.x + b2.x;
        y2.y = (o[n][3] * zi2 - mu2) * rs2 * g2.y + b2.y;
        *reinterpret_cast<float2*>(orow1 + cb) = y1;
        *reinterpret_cast<float2*>(orow2 + cb) = y2;
    }
}

extern "C" void kernel_launch(void* const* d_in, const int* in_sizes, int n_in,
                              void* d_out, int out_size) {
    (void)in_sizes; (void)n_in; (void)out_size;
    const float* q     = (const float*)d_in[0];
    const float* k     = (const float*)d_in[1];
    const float* v     = (const float*)d_in[2];
    const float* mask  = (const float*)d_in[3];
    const float* gamma = (const float*)d_in[4];
    const float* beta  = (const float*)d_in[5];
    float* out = (float*)d_out;

    cudaFuncSetAttribute(fmha_ln_hmma, cudaFuncAttributeMaxDynamicSharedMemorySize, SMEM_BYTES);
    fmha_ln_hmma<<<dim3(LSEQ / TQ, BATCH), 256, SMEM_BYTES>>>(q, k, v, mask, gamma, beta, out);
}

// round 6
// speedup vs baseline: 1.6899x; 1.6899x over previous
#include <cuda_runtime.h>
#include <cuda_bf16.h>
#include <stdint.h>

// Plain-sm_103-legal: HMMA mma.sync + ldmatrix + cp.async. No tcgen05.
// R6: prep-split Q/K/V to bf16 hi/lo in gmem; double-buffered cp.async staging
// (TKN=64); ldmatrix.x4 for K and V fragments (half the LDSM issue).

static constexpr int BATCH = 16;
static constexpr int LSEQ  = 2048;
static constexpr int DHEAD = 128;
static constexpr int TQ    = 128;   // q rows per CTA
static constexpr int TKN   = 64;    // keys per tile (double-buffered)
static constexpr int NKT   = LSEQ / TKN;   // 32

static constexpr int PAD   = 136;   // bf16 elems per smem row (272B, conflict-free ldsm)
// smem byte layout
static constexpr int QT_BYTES = TQ  * PAD * 2;   // 34816
static constexpr int KT_BYTES = TKN * PAD * 2;   // 17408
static constexpr int SQH = 0;
static constexpr int SQL = QT_BYTES;
static constexpr int SBUF0 = 2 * QT_BYTES;               // 69632
static constexpr int BUF_STRIDE = 4 * KT_BYTES;          // 69632 (KH,KL,VH,VL)
static constexpr int OKH = 0, OKL = KT_BYTES, OVH = 2 * KT_BYTES, OVL = 3 * KT_BYTES;
static constexpr int SMEM_BYTES = SBUF0 + 2 * BUF_STRIDE;  // 208896

// prepped bf16 hi/lo tensors [B][L][128]
__device__ __align__(16) __nv_bfloat16 g_qh[(size_t)BATCH * LSEQ * DHEAD];
__device__ __align__(16) __nv_bfloat16 g_ql[(size_t)BATCH * LSEQ * DHEAD];
__device__ __align__(16) __nv_bfloat16 g_kh[(size_t)BATCH * LSEQ * DHEAD];
__device__ __align__(16) __nv_bfloat16 g_kl[(size_t)BATCH * LSEQ * DHEAD];
__device__ __align__(16) __nv_bfloat16 g_vh[(size_t)BATCH * LSEQ * DHEAD];
__device__ __align__(16) __nv_bfloat16 g_vl[(size_t)BATCH * LSEQ * DHEAD];

// ---------------- helpers ----------------
__device__ __forceinline__ uint32_t smem_u32(const void* p) {
    uint32_t a;
    asm("{ .reg .u64 t; cvta.to.shared.u64 t, %1; cvt.u32.u64 %0, t; }" : "=r"(a) : "l"(p));
    return a;
}
__device__ __forceinline__ uint32_t pack2(__nv_bfloat16 a, __nv_bfloat16 b) {
    return (uint32_t)__bfloat16_as_ushort(a) | ((uint32_t)__bfloat16_as_ushort(b) << 16);
}
__device__ __forceinline__ void ldsm_x4(uint32_t* r, uint32_t addr) {
    asm volatile("ldmatrix.sync.aligned.m8n8.x4.shared.b16 {%0,%1,%2,%3}, [%4];"
                 : "=r"(r[0]), "=r"(r[1]), "=r"(r[2]), "=r"(r[3]) : "r"(addr));
}
__device__ __forceinline__ void ldsm_x4_t(uint32_t* r, uint32_t addr) {
    asm volatile("ldmatrix.sync.aligned.m8n8.x4.trans.shared.b16 {%0,%1,%2,%3}, [%4];"
                 : "=r"(r[0]), "=r"(r[1]), "=r"(r[2]), "=r"(r[3]) : "r"(addr));
}
__device__ __forceinline__ void mma16816(float* d, const uint32_t* a, const uint32_t* b) {
    asm volatile("mma.sync.aligned.m16n8k16.row.col.f32.bf16.bf16.f32 "
                 "{%0,%1,%2,%3}, {%4,%5,%6,%7}, {%8,%9}, {%0,%1,%2,%3};"
                 : "+f"(d[0]), "+f"(d[1]), "+f"(d[2]), "+f"(d[3])
                 : "r"(a[0]), "r"(a[1]), "r"(a[2]), "r"(a[3]), "r"(b[0]), "r"(b[1]));
}
__device__ __forceinline__ void cp16(uint32_t dst, const void* src) {
    asm volatile("cp.async.cg.shared.global [%0], [%1], 16;" :: "r"(dst), "l"(src));
}
#define CP_COMMIT() asm volatile("cp.async.commit_group;" ::: "memory")

// stage a TKN x 128 bf16 tile (row-major, 128 contig) into padded smem (async)
__device__ __forceinline__ void stage64(uint32_t dstb, const __nv_bfloat16* __restrict__ g, int tid) {
    #pragma unroll
    for (int i = 0; i < 4; ++i) {                  // 1024 chunks / 256 threads
        int idx = tid + i * 256;
        int row = idx >> 4, c = idx & 15;
        cp16(dstb + row * (PAD * 2) + c * 16, g + row * DHEAD + c * 8);
    }
}
__device__ __forceinline__ void stage128(uint32_t dstb, const __nv_bfloat16* __restrict__ g, int tid) {
    #pragma unroll
    for (int i = 0; i < 8; ++i) {                  // 2048 chunks / 256 threads
        int idx = tid + i * 256;
        int row = idx >> 4, c = idx & 15;
        cp16(dstb + row * (PAD * 2) + c * 16, g + row * DHEAD + c * 8);
    }
}

// -------- prep: fp32 -> bf16 hi/lo for Q,K,V --------
__device__ __forceinline__ void split4(float4 f, __nv_bfloat16* hi, __nv_bfloat16* lo, size_t i4) {
    __nv_bfloat16 h0 = __float2bfloat16_rn(f.x), h1 = __float2bfloat16_rn(f.y);
    __nv_bfloat16 h2 = __float2bfloat16_rn(f.z), h3 = __float2bfloat16_rn(f.w);
    *reinterpret_cast<uint2*>(hi + 4 * i4) = make_uint2(pack2(h0, h1), pack2(h2, h3));
    *reinterpret_cast<uint2*>(lo + 4 * i4) = make_uint2(
        pack2(__float2bfloat16_rn(f.x - __bfloat162float(h0)), __float2bfloat16_rn(f.y - __bfloat162float(h1))),
        pack2(__float2bfloat16_rn(f.z - __bfloat162float(h2)), __float2bfloat16_rn(f.w - __bfloat162float(h3))));
}
__global__ void prep_split(const float* __restrict__ q, const float* __restrict__ k,
                           const float* __restrict__ v) {
    size_t i = (size_t)blockIdx.x * blockDim.x + threadIdx.x;   // float4 index
    split4(reinterpret_cast<const float4*>(q)[i], g_qh, g_ql, i);
    split4(reinterpret_cast<const float4*>(k)[i], g_kh, g_kl, i);
    split4(reinterpret_cast<const float4*>(v)[i], g_vh, g_vl, i);
}

// -------- fused attention + layernorm --------
__global__ void __launch_bounds__(256, 1)
fmha_ln_hmma(const float* __restrict__ MASK, const float* __restrict__ GAMMA,
             const float* __restrict__ BETA, float* __restrict__ OUT) {
    extern __shared__ char sm[];
    const int tid = threadIdx.x;
    const int w   = tid >> 5;
    const int l   = tid & 31;
    const int b   = blockIdx.y;
    const int q0  = blockIdx.x * TQ;

    const int qr  = l >> 2;
    const int qc2 = (l & 3) * 2;
    const int r1  = 16 * w + qr;

    const uint32_t smb = smem_u32(sm);

    // per-lane ldmatrix offsets (bytes)
    const int lr = l & 7, g = l >> 3;
    // A (x4 non-trans): groups: rowL/kL, rowH/kL, rowL/kH, rowH/kH
    const int a_row = 16 * w + lr + ((g & 1) << 3);
    const uint32_t a_off = (uint32_t)(a_row * PAD + ((g >> 1) << 3)) * 2;
    // K B-frag x4 (n-pair): g0 nL/kL, g1 nL/kH, g2 nH/kL, g3 nH/kH
    const uint32_t kb4_off = (uint32_t)((lr + ((g >> 1) << 3)) * PAD + ((g & 1) << 3)) * 2;
    // V B-frag x4 trans (d-pair): g0 kL/dL, g1 kH/dL, g2 kL/dH, g3 kH/dH
    const uint32_t vb4_off = (uint32_t)((lr + ((g & 1) << 3)) * PAD + ((g >> 1) << 3)) * 2;

    const size_t qgbase = ((size_t)(b * LSEQ + q0)) * DHEAD;
    const size_t kvbase = ((size_t)b * LSEQ) * DHEAD;

    // prologue: Q hi/lo + tile 0 (one cp.async group)
    stage128(smb + SQH, g_qh + qgbase, tid);
    stage128(smb + SQL, g_ql + qgbase, tid);
    {
        const uint32_t d0 = smb + SBUF0;
        const size_t t0 = kvbase;
        stage64(d0 + OKH, g_kh + t0, tid);
        stage64(d0 + OKL, g_kl + t0, tid);
        stage64(d0 + OVH, g_vh + t0, tid);
        stage64(d0 + OVL, g_vl + t0, tid);
    }
    CP_COMMIT();

    float o[16][4];
    #pragma unroll
    for (int n = 0; n < 16; ++n) { o[n][0] = o[n][1] = o[n][2] = o[n][3] = 0.f; }
    float Z1 = 0.f, Z2 = 0.f;

    const float* mrow1 = MASK + (size_t)(q0 + r1) * LSEQ;
    const float* mrow2 = mrow1 + 8 * LSEQ;

    #pragma unroll 1
    for (int kt = 0; kt < NKT; ++kt) {
        // issue next tile, then wait for current
        if (kt + 1 < NKT) {
            const uint32_t dn = smb + SBUF0 + ((kt + 1) & 1) * BUF_STRIDE;
            const size_t tn = kvbase + (size_t)(kt + 1) * TKN * DHEAD;
            stage64(dn + OKH, g_kh + tn, tid);
            stage64(dn + OKL, g_kl + tn, tid);
            stage64(dn + OVH, g_vh + tn, tid);
            stage64(dn + OVL, g_vl + tn, tid);
            CP_COMMIT();
            asm volatile("cp.async.wait_group 1;" ::: "memory");
        } else {
            asm volatile("cp.async.wait_group 0;" ::: "memory");
        }
        __syncthreads();

        const uint32_t bufb = smb + SBUF0 + (kt & 1) * BUF_STRIDE;
        const uint32_t kh = bufb + OKH, kl = bufb + OKL;
        const uint32_t vh = bufb + OVH, vl = bufb + OVL;

        // ---- S = Qhi*Khi + Qhi*Klo + Qlo*Khi ----
        float c[8][4];
        #pragma unroll
        for (int n = 0; n < 8; ++n) { c[n][0] = c[n][1] = c[n][2] = c[n][3] = 0.f; }

        #pragma unroll
        for (int kk = 0; kk < 8; ++kk) {
            uint32_t aH[4], aL[4];
            ldsm_x4(aH, smb + SQH + a_off + kk * 32);
            ldsm_x4(aL, smb + SQL + a_off + kk * 32);
            #pragma unroll
            for (int p = 0; p < 4; ++p) {
                const uint32_t toff = (uint32_t)(p * 16 * PAD + kk * 16) * 2;
                uint32_t bH[4], bL[4];
                ldsm_x4(bH, kh + kb4_off + toff);
                ldsm_x4(bL, kl + kb4_off + toff);
                mma16816(c[2 * p + 0], aH, bH + 0);
                mma16816(c[2 * p + 0], aH, bL + 0);
                mma16816(c[2 * p + 0], aL, bH + 0);
                mma16816(c[2 * p + 1], aH, bH + 2);
                mma16816(c[2 * p + 1], aH, bL + 2);
                mma16816(c[2 * p + 1], aL, bH + 2);
            }
        }

        // ---- P = exp(S + mask); pack A-frags; accumulate Z ----
        uint32_t phi[4][4], plo[4][4];
        #pragma unroll
        for (int n = 0; n < 8; ++n) {
            const int cb = kt * TKN + 8 * n + qc2;
            const float2 m1 = *reinterpret_cast<const float2*>(mrow1 + cb);
            const float2 m2 = *reinterpret_cast<const float2*>(mrow2 + cb);
            float e0 = __expf(c[n][0] + m1.x);
            float e1 = __expf(c[n][1] + m1.y);
            float e2 = __expf(c[n][2] + m2.x);
            float e3 = __expf(c[n][3] + m2.y);
            Z1 += e0 + e1;
            Z2 += e2 + e3;
            __nv_bfloat16 h0 = __float2bfloat16_rn(e0), h1 = __float2bfloat16_rn(e1);
            __nv_bfloat16 h2 = __float2bfloat16_rn(e2), h3 = __float2bfloat16_rn(e3);
            const int s = n >> 1, hh = (n & 1) * 2;
            phi[s][hh + 0] = pack2(h0, h1);
            phi[s][hh + 1] = pack2(h2, h3);
            plo[s][hh + 0] = pack2(__float2bfloat16_rn(e0 - __bfloat162float(h0)),
                                   __float2bfloat16_rn(e1 - __bfloat162float(h1)));
            plo[s][hh + 1] = pack2(__float2bfloat16_rn(e2 - __bfloat162float(h2)),
                                   __float2bfloat16_rn(e3 - __bfloat162float(h3)));
        }

        // ---- O += Phi*Vhi + Plo*Vhi + Phi*Vlo ----
        #pragma unroll
        for (int dp = 0; dp < 8; ++dp) {
            #pragma unroll
            for (int s = 0; s < 4; ++s) {
                const uint32_t toff = (uint32_t)(s * 16 * PAD + dp * 16) * 2;
                uint32_t bH[4], bL[4];
                ldsm_x4_t(bH, vh + vb4_off + toff);
                ldsm_x4_t(bL, vl + vb4_off + toff);
                mma16816(o[2 * dp + 0], phi[s], bH + 0);
                mma16816(o[2 * dp + 0], plo[s], bH + 0);
                mma16816(o[2 * dp + 0], phi[s], bL + 0);
                mma16816(o[2 * dp + 1], phi[s], bH + 2);
                mma16816(o[2 * dp + 1], plo[s], bH + 2);
                mma16816(o[2 * dp + 1], phi[s], bL + 2);
            }
        }
        __syncthreads();   // readers done before next stage overwrites this buffer's twin
    }

    // ---- quad-reduce Z; LayerNorm; write ----
    Z1 += __shfl_xor_sync(0xffffffffu, Z1, 1);
    Z1 += __shfl_xor_sync(0xffffffffu, Z1, 2);
    Z2 += __shfl_xor_sync(0xffffffffu, Z2, 1);
    Z2 += __shfl_xor_sync(0xffffffffu, Z2, 2);
    const float zi1 = 1.0f / Z1, zi2 = 1.0f / Z2;

    float s1a = 0.f, s1b = 0.f, s2a = 0.f, s2b = 0.f;
    #pragma unroll
    for (int n = 0; n < 16; ++n) {
        float x0 = o[n][0] * zi1, x1 = o[n][1] * zi1;
        float x2 = o[n][2] * zi2, x3 = o[n][3] * zi2;
        s1a += x0 + x1;  s1b += x0 * x0 + x1 * x1;
        s2a += x2 + x3;  s2b += x2 * x2 + x3 * x3;
    }
    s1a += __shfl_xor_sync(0xffffffffu, s1a, 1); s1a += __shfl_xor_sync(0xffffffffu, s1a, 2);
    s1b += __shfl_xor_sync(0xffffffffu, s1b, 1); s1b += __shfl_xor_sync(0xffffffffu, s1b, 2);
    s2a += __shfl_xor_sync(0xffffffffu, s2a, 1); s2a += __shfl_xor_sync(0xffffffffu, s2a, 2);
    s2b += __shfl_xor_sync(0xffffffffu, s2b, 1); s2b += __shfl_xor_sync(0xffffffffu, s2b, 2);

    const float mu1 = s1a * (1.0f / 128.0f);
    const float v1  = fmaxf(s1b * (1.0f / 128.0f) - mu1 * mu1, 0.0f);
    const float rs1 = rsqrtf(v1 + 1e-5f);
    const float mu2 = s2a * (1.0f / 128.0f);
    const float v2  = fmaxf(s2b * (1.0f / 128.0f) - mu2 * mu2, 0.0f);
    const float rs2 = rsqrtf(v2 + 1e-5f);

    float* orow1 = OUT + ((size_t)(b * LSEQ + q0 + r1)) * DHEAD;
    float* orow2 = orow1 + 8 * DHEAD;
    #pragma unroll
    for (int n = 0; n < 16; ++n) {
        const int cb = 8 * n + qc2;
        const float2 g2 = *reinterpret_cast<const float2*>(GAMMA + cb);
        const float2 b2 = *reinterpret_cast<const float2*>(BETA + cb);
        float2 y1, y2;
        y1.x = (o[n][0] * zi1 - mu1) * rs1 * g2.x + b2.x;
        y1.y = (o[n][1] * zi1 - mu1) * rs1 * g2.y + b2.y;
        y2.x = (o[n][2] * zi2 - mu2) * rs2 * g2.x + b2.x;
        y2.y = (o[n][3] * zi2 - mu2) * rs2 * g2.y + b2.y;
        *reinterpret_cast<float2*>(orow1 + cb) = y1;
        *reinterpret_cast<float2*>(orow2 + cb) = y2;
    }
}

extern "C" void kernel_launch(void* const* d_in, const int* in_sizes, int n_in,
                              void* d_out, int out_size) {
    (void)in_sizes; (void)n_in; (void)out_size;
    const float* q     = (const float*)d_in[0];
    const float* k     = (const float*)d_in[1];
    const float* v     = (const float*)d_in[2];
    const float* mask  = (const float*)d_in[3];
    const float* gamma = (const float*)d_in[4];
    const float* beta  = (const float*)d_in[5];
    float* out = (float*)d_out;

    cudaFuncSetAttribute(fmha_ln_hmma, cudaFuncAttributeMaxDynamicSharedMemorySize, SMEM_BYTES);

    const int total_f4 = BATCH * LSEQ * DHEAD / 4;          // per tensor
    prep_split<<<total_f4 / 256, 256>>>(q, k, v);
    fmha_ln_hmma<<<dim3(LSEQ / TQ, BATCH), 256, SMEM_BYTES>>>(mask, gamma, beta, out);
}